// round 2
// baseline (speedup 1.0000x reference)
#include <cuda_runtime.h>
#include <stdint.h>

#define V_N    1024
#define EDGE_N 6144
#define MAXD   64            // safe upper bound on vnode degree (Poisson(6), max@1024 ~ 17)
#define NCHUNK 32
#define CHUNK  (EDGE_N / NCHUNK)   // 192

// ---- static device scratch (no allocation allowed) ----
__device__ int g_e2v[EDGE_N];
__device__ int g_cnt[NCHUNK * V_N];
__device__ __align__(16) int g_deg[V_N];
__device__ __align__(16) uint16_t g_ell[MAXD * V_N];   // column-major ELL: ell[j*V_N + v]

// K1: recover edge -> vnode from the one-hot mask rows.
__global__ void k_e2v(const float* __restrict__ mask) {
    int stride = gridDim.x * blockDim.x;
    for (int i = blockIdx.x * blockDim.x + threadIdx.x; i < EDGE_N * V_N; i += stride)
        if (mask[i] != 0.0f) g_e2v[i >> 10] = (i & (V_N - 1));
}

// K2: fill ELL with sentinel (EDGE_N -> reads stage[EDGE_N] == 0.0f in main kernel)
__global__ void k_fill() {
    int stride = gridDim.x * blockDim.x;
    for (int j = blockIdx.x * blockDim.x + threadIdx.x; j < MAXD * V_N; j += stride)
        g_ell[j] = (uint16_t)EDGE_N;
}

// K3: per-(chunk, vnode) occurrence counts — fully deterministic.
__global__ void k_count() {
    int id = blockIdx.x * blockDim.x + threadIdx.x;
    if (id >= NCHUNK * V_N) return;
    int c = id >> 10;                // chunk   (V_N == 1024)
    int v = id & (V_N - 1);          // vnode
    int base = c * CHUNK;
    int cnt = 0;
    #pragma unroll 4
    for (int k = 0; k < CHUNK; ++k)
        cnt += (g_e2v[base + k] == v);
    g_cnt[c * V_N + v] = cnt;
}

// K4: place edge ids into ELL in deterministic (ascending edge) order; emit degrees.
__global__ void k_place() {
    int id = blockIdx.x * blockDim.x + threadIdx.x;
    if (id >= NCHUNK * V_N) return;
    int c = id >> 10;
    int v = id & (V_N - 1);
    int pos = 0;
    for (int cc = 0; cc < c; ++cc) pos += g_cnt[cc * V_N + v];
    if (c == NCHUNK - 1) g_deg[v] = pos + g_cnt[c * V_N + v];
    int base = c * CHUNK;
    for (int k = 0; k < CHUNK; ++k) {
        int e = base + k;
        if (g_e2v[e] == v) { g_ell[pos * V_N + v] = (uint16_t)e; ++pos; }
    }
}

// Main: one block per batch row. Stage from_prev row in SMEM (coalesced),
// thread t owns vnodes 4t..4t+3; ushort4 ELL index loads are fully coalesced
// and L1-resident; sentinel column (stage[EDGE_N]=0) makes padding branch-free.
__global__ __launch_bounds__(256, 8) void k_main(
    const float* __restrict__ fin, const float* __restrict__ fprev,
    float* __restrict__ out)
{
    __shared__ __align__(16) float stage[EDGE_N + 4];
    int t = threadIdx.x;
    long long b = blockIdx.x;

    const float4* fp4 = (const float4*)(fprev + b * EDGE_N);
    float4* st4 = (float4*)stage;
    #pragma unroll
    for (int i = 0; i < EDGE_N / 1024; ++i)          // 6 x 256 threads x float4 = 6144
        st4[i * 256 + t] = fp4[i * 256 + t];
    if (t == 0) stage[EDGE_N] = 0.0f;

    float4 s = ((const float4*)(fin + b * V_N))[t];
    int4 dg = ((const int4*)g_deg)[t];
    int md = max(max(dg.x, dg.y), max(dg.z, dg.w));

    __syncthreads();

    const ushort4* ellp = (const ushort4*)g_ell;     // row j = 256 ushort4
    #pragma unroll 2
    for (int j = 0; j < md; ++j) {
        ushort4 e = ellp[j * (V_N / 4) + t];
        s.x += stage[e.x];
        s.y += stage[e.y];
        s.z += stage[e.z];
        s.w += stage[e.w];
    }

    ((float4*)(out + b * V_N))[t] = s;
}

extern "C" void kernel_launch(void* const* d_in, const int* in_sizes, int n_in,
                              void* d_out, int out_size) {
    const float* fin   = (const float*)d_in[0];   // [B, V_N]
    const float* fprev = (const float*)d_in[1];   // [B, EDGE_N]
    const float* mask  = (const float*)d_in[2];   // [EDGE_N, V_N]
    int B = in_sizes[0] / V_N;

    k_e2v  <<<592, 256>>>(mask);
    k_fill <<<64, 256>>>();
    k_count<<<(NCHUNK * V_N) / 256, 256>>>();
    k_place<<<(NCHUNK * V_N) / 256, 256>>>();
    k_main <<<B, 256>>>(fin, fprev, (float*)d_out);
}

// round 5
// speedup vs baseline: 1.1778x; 1.1778x over previous
#include <cuda_runtime.h>
#include <stdint.h>

#define V_N    1024
#define EDGE_N 6144
#define MAXD   64

// ---- static device scratch (no allocation allowed) ----
__device__ uint16_t g_e2v[EDGE_N];
__device__ __align__(16) int g_deg[V_N];
__device__ __align__(16) uint16_t g_ell[MAXD * V_N];   // column-major ELL: ell[j*V_N + v]

// K1: sentinel-fill ELL, zero degrees, recover edge->vnode from one-hot mask.
__global__ void k_prep(const float4* __restrict__ mask4) {
    int stride = gridDim.x * blockDim.x;
    int tid0 = blockIdx.x * blockDim.x + threadIdx.x;
    for (int i = tid0; i < MAXD * V_N; i += stride) g_ell[i] = (uint16_t)EDGE_N;
    for (int i = tid0; i < V_N; i += stride) g_deg[i] = 0;
    // mask is EDGE_N*V_N floats = 1572864 float4
    for (int i = tid0; i < (EDGE_N * V_N) / 4; i += stride) {
        float4 m = mask4[i];
        int base = i * 4;
        if (m.x != 0.0f) g_e2v[base >> 10]       = (uint16_t)( base      & (V_N - 1));
        if (m.y != 0.0f) g_e2v[(base + 1) >> 10] = (uint16_t)((base + 1) & (V_N - 1));
        if (m.z != 0.0f) g_e2v[(base + 2) >> 10] = (uint16_t)((base + 2) & (V_N - 1));
        if (m.w != 0.0f) g_e2v[(base + 3) >> 10] = (uint16_t)((base + 3) & (V_N - 1));
    }
}

// K2: one WARP per edge. rank(e) = |{e' < e : e2v[e']==e2v[e]}| via lane-strided
// smem scan + warp reduce. Deterministic: same ascending-edge order as a serial
// stable placement; g_deg via integer atomics (order-independent result).
__global__ __launch_bounds__(256) void k_build() {
    __shared__ uint16_t se[EDGE_N];
    int t = threadIdx.x;
    const uint32_t* src = (const uint32_t*)g_e2v;
    uint32_t* dst = (uint32_t*)se;
    #pragma unroll
    for (int i = 0; i < EDGE_N / 2 / 256; ++i)       // 3072 u32 words
        dst[i * 256 + t] = src[i * 256 + t];
    __syncthreads();

    int e = (blockIdx.x * blockDim.x + t) >> 5;      // global warp id == edge id
    int lane = t & 31;
    if (e < EDGE_N) {
        int v = se[e];
        int cnt = 0;
        for (int i = lane; i < e; i += 32) cnt += (se[i] == v);
        cnt = __reduce_add_sync(0xffffffff, cnt);
        if (lane == 0) {
            g_ell[cnt * V_N + v] = (uint16_t)e;
            atomicAdd(&g_deg[v], 1);
        }
    }
}

// Main: one block per PAIR of batch rows. Stage both rows interleaved as
// float2{row0[e], row1[e]} so each random LDS.64 feeds two rows' accumulators.
// Thread t owns vnodes 4t..4t+3; ushort4 index loads coalesced & L1-resident;
// sentinel slot stage[EDGE_N]={0,0} makes ELL padding branch-free.
__global__ __launch_bounds__(256) void k_main(
    const float* __restrict__ fin, const float* __restrict__ fprev,
    float* __restrict__ out, int B)
{
    extern __shared__ __align__(16) float2 stage[];  // EDGE_N+1 float2 = 49160 B
    int t = threadIdx.x;
    long long b0 = (long long)blockIdx.x * 2;
    long long b1 = (b0 + 1 < B) ? b0 + 1 : b0;

    const float4* r0 = (const float4*)(fprev + b0 * EDGE_N);
    const float4* r1 = (const float4*)(fprev + b1 * EDGE_N);
    #pragma unroll
    for (int i = 0; i < EDGE_N / 1024; ++i) {        // 6 chunks
        float4 a = r0[i * 256 + t];
        float4 c = r1[i * 256 + t];
        float4* d = (float4*)&stage[(i * 256 + t) * 4];
        d[0] = make_float4(a.x, c.x, a.y, c.y);
        d[1] = make_float4(a.z, c.z, a.w, c.w);
    }
    if (t == 0) stage[EDGE_N] = make_float2(0.0f, 0.0f);

    float4 s0 = ((const float4*)(fin + b0 * V_N))[t];
    float4 s1 = ((const float4*)(fin + b1 * V_N))[t];
    int4 dg = ((const int4*)g_deg)[t];
    int md = max(max(dg.x, dg.y), max(dg.z, dg.w));

    __syncthreads();

    const ushort4* ellp = (const ushort4*)g_ell;
    #pragma unroll 2
    for (int j = 0; j < md; ++j) {
        ushort4 e = ellp[j * (V_N / 4) + t];
        float2 vx = stage[e.x]; s0.x += vx.x; s1.x += vx.y;
        float2 vy = stage[e.y]; s0.y += vy.x; s1.y += vy.y;
        float2 vz = stage[e.z]; s0.z += vz.x; s1.z += vz.y;
        float2 vw = stage[e.w]; s0.w += vw.x; s1.w += vw.y;
    }

    ((float4*)(out + b0 * V_N))[t] = s0;
    ((float4*)(out + b1 * V_N))[t] = s1;
}

extern "C" void kernel_launch(void* const* d_in, const int* in_sizes, int n_in,
                              void* d_out, int out_size) {
    const float* fin   = (const float*)d_in[0];   // [B, V_N]
    const float* fprev = (const float*)d_in[1];   // [B, EDGE_N]
    const float* mask  = (const float*)d_in[2];   // [EDGE_N, V_N]
    int B = in_sizes[0] / V_N;

    static const int kSmem = (EDGE_N + 1) * sizeof(float2);   // 49160 > 48K static limit
    cudaFuncSetAttribute(k_main, cudaFuncAttributeMaxDynamicSharedMemorySize, kSmem);

    k_prep <<<592, 256>>>((const float4*)mask);
    k_build<<<(EDGE_N * 32) / 256, 256>>>();
    k_main <<<(B + 1) / 2, 256, kSmem>>>(fin, fprev, (float*)d_out, B);
}